// round 17
// baseline (speedup 1.0000x reference)
#include <cuda_runtime.h>
#include <cfloat>
#include <climits>
#include <math.h>

#define NPTS     4096
#define G_TOTAL  65536
#define NBUCK    64
#define INV_CELL (1.0f / 16.0f)
#define NEG_INF_F (__int_as_float(0xff800000))

#define BLOCK_T  512    // threads per block
#define GPTS     256    // grid points per block (one grid row)
#define NBLK     (G_TOTAL / GPTS)   // 256 blocks; 2 CTAs/SM -> all resident
#define CAPB     16     // per-x-bucket capacity
#define OCAP     64     // x overflow list capacity
#define PAD      0.25f  // covers reference d2 rounding slack

// Lexicographic (d2, pid) top-4 insertion. sqrt is monotone in d2, so this
// matches the reference's (d, idx) top_k ordering (verified rel_err=0.0);
// sqrt is deferred to finalize.
__device__ __forceinline__ void insert4(
    float d2, int pid, float sc,
    float& da, float& db, float& dc, float& dd,
    int& ia, int& ib, int& ic, int& id_,
    float& sa, float& sb, float& sc_, float& sd)
{
    if (d2 < dd || (d2 == dd && pid < id_)) {
        dd = d2; id_ = pid; sd = sc;
        if (dd < dc || (dd == dc && id_ < ic)) {
            float td = dc; int ti = ic; float ts = sc_;
            dc = dd; ic = id_; sc_ = sd;
            dd = td; id_ = ti; sd = ts;
            if (dc < db || (dc == db && ic < ib)) {
                td = db; ti = ib; ts = sb;
                db = dc; ib = ic; sb = sc_;
                dc = td; ic = ti; sc_ = ts;
                if (db < da || (db == da && ib < ia)) {
                    td = da; ti = ia; ts = sa;
                    da = db; ia = ib; sa = sb;
                    db = td; ib = ti; sb = ts;
                }
            }
        }
    }
}

// ---------------------------------------------------------------------------
// 256 blocks x 512 threads (2 CTAs/SM, all resident). One grid row per block.
// Front batch: grid/accu/scale/code + pos.xy (float2 x4) + scores (x4),
// all independent, before the single pre-phase-A barrier.
// Phase A: all 512 threads bin y-strip survivors into smem x-buckets;
//          bucket index / p2 / packing hoisted out of the survivor branch
//          (FMA/ALU pipes are idle; overlaps atomic/STS latency).
// Phase B: threads 0..255 walk their 2-3 bucket window (few candidates).
// Phase C: stage output rows in smem (overlaying s_buck), flush the
//          contiguous 6 KB span with coalesced float4 stores.
// ---------------------------------------------------------------------------
__global__ void __launch_bounds__(BLOCK_T, 2) pump_fused_kernel(
    const float4* __restrict__ pos,      // (NPTS, 4)
    const float*  __restrict__ scores,   // (NPTS,)
    const float2* __restrict__ grid,     // (G, 2)
    const float*  __restrict__ accu,     // (G, 6)
    const float*  __restrict__ scale_p,
    const float*  __restrict__ code_p,
    float*        __restrict__ out)      // (G, 6)
{
    __shared__ float4 s_buck[NBUCK * CAPB];   // reused as output staging
    __shared__ int    s_bpid[NBUCK * CAPB];
    __shared__ int    s_cnt[NBUCK];
    __shared__ float4 s_ovf[OCAP];
    __shared__ int    s_opid[OCAP];
    __shared__ int    s_ocnt, s_fb;
    __shared__ float  s_wmin[GPTS / 32], s_wmax[GPTS / 32];

    const int tid = threadIdx.x;
    const int lane = tid & 31;
    const int warp = tid >> 5;
    const bool is_g = (tid < GPTS);
    const int g = blockIdx.x * GPTS + (is_g ? tid : 0);

    // ---- front batch: every independent gmem load ----
    const float scale = __ldg(scale_p);
    const float code  = __ldg(code_p);

    float gx = 0.0f, gy = 0.0f;
    float2 a01, a23, a45;
    const float2* acc2 = (const float2*)accu;
    if (is_g) {
        const float2 gp = grid[g];
        gx = gp.x; gy = gp.y;
        a01 = acc2[g * 3 + 0];
        a23 = acc2[g * 3 + 1];
        a45 = acc2[g * 3 + 2];
    }

    // pos.xy only (stride-16 float2).
    const float2* pos2 = (const float2*)pos;
    float2 pxy[NPTS / BLOCK_T];
    float  sbuf[NPTS / BLOCK_T];
    #pragma unroll
    for (int i = 0; i < NPTS / BLOCK_T; i++) {
        const int idx = tid + i * BLOCK_T;
        pxy[i]  = pos2[idx * 2];
        sbuf[i] = __ldg(&scores[idx]);
    }

    const float g2 = __fadd_rn(__fmul_rn(gx, gx), __fmul_rn(gy, gy));
    const float dist_max = __fsub_rn(__fmul_rn(8.0f, scale), 1e-7f);
    const float rp = dist_max + PAD;

    // ---- init + per-warp y-range, ONE barrier ----
    if (tid < NBUCK) s_cnt[tid] = 0;
    if (tid == 0) { s_ocnt = 0; s_fb = 0; }
    if (is_g) {
        float lo = gy, hi = gy;
        #pragma unroll
        for (int o = 16; o > 0; o >>= 1) {
            lo = fminf(lo, __shfl_xor_sync(0xffffffffu, lo, o));
            hi = fmaxf(hi, __shfl_xor_sync(0xffffffffu, hi, o));
        }
        if (lane == 0) { s_wmin[warp] = lo; s_wmax[warp] = hi; }
    }
    __syncthreads();

    float blo = s_wmin[0], bhi = s_wmax[0];
    #pragma unroll
    for (int w = 1; w < GPTS / 32; w++) {
        blo = fminf(blo, s_wmin[w]);
        bhi = fmaxf(bhi, s_wmax[w]);
    }
    const float ylo = blo - rp;
    const float yhi = bhi + rp;

    // ---- Phase A: bin survivors into x-buckets (hoisted computation) ----
    #pragma unroll
    for (int i = 0; i < NPTS / BLOCK_T; i++) {
        const float px = pxy[i].x, py = pxy[i].y;
        // Hoisted: everything below depends only on resident registers and
        // overlaps the previous iteration's atomic/STS latency.
        const int idx = tid + i * BLOCK_T;
        int bx = (int)floorf(px * INV_CELL);
        bx = min(NBUCK - 1, max(0, bx));
        const float p2 = __fadd_rn(__fmul_rn(px, px), __fmul_rn(py, py));
        const float4 e = make_float4(px, py, p2, sbuf[i]);
        if (py > ylo && py < yhi) {
            const int slot = atomicAdd(&s_cnt[bx], 1);
            if (slot < CAPB) {
                s_buck[bx * CAPB + slot] = e;
                s_bpid[bx * CAPB + slot] = idx;
            } else {
                const int o = atomicAdd(&s_ocnt, 1);
                if (o < OCAP) { s_ovf[o] = e; s_opid[o] = idx; }
                else s_fb = 1;   // pathological input: full-scan fallback
            }
        }
    }
    __syncthreads();
    const int fb = s_fb;

    // ---- Phase B: top-4 by (d2, pid) over the padded x-window ----
    float r0 = 0, r1 = 0, r2 = 0, r3 = 0, r4 = 0, r5 = 0;  // output row
    if (is_g) {
        float da = FLT_MAX, db = FLT_MAX, dc = FLT_MAX, dd = FLT_MAX;
        int   ia = INT_MAX, ib = INT_MAX, ic = INT_MAX, id_ = INT_MAX;
        float sa = 0.0f,    sb = 0.0f,    sc_ = 0.0f,   sd = 0.0f;

        if (!fb) {
            int bx0 = (int)floorf((gx - rp) * INV_CELL);
            int bx1 = (int)floorf((gx + rp) * INV_CELL);
            bx0 = min(NBUCK - 1, max(0, bx0));
            bx1 = min(NBUCK - 1, max(0, bx1));

            for (int bx = bx0; bx <= bx1; bx++) {
                const int n = min(s_cnt[bx], CAPB);
                const int base = bx * CAPB;
                for (int k = 0; k < n; k++) {
                    const float4 e = s_buck[base + k];
                    const int pid = s_bpid[base + k];
                    const float dot = __fmaf_rn(e.y, gy, __fmul_rn(e.x, gx));
                    const float d2 = __fsub_rn(__fadd_rn(e.z, g2),
                                               __fmul_rn(2.0f, dot));
                    insert4(d2, pid, e.w, da, db, dc, dd, ia, ib, ic, id_,
                            sa, sb, sc_, sd);
                }
            }
            const int on = min(s_ocnt, OCAP);
            for (int k = 0; k < on; k++) {
                const float4 e = s_ovf[k];
                const int pid = s_opid[k];
                const float dot = __fmaf_rn(e.y, gy, __fmul_rn(e.x, gx));
                const float d2 = __fsub_rn(__fadd_rn(e.z, g2),
                                           __fmul_rn(2.0f, dot));
                insert4(d2, pid, e.w, da, db, dc, dd, ia, ib, ic, id_,
                        sa, sb, sc_, sd);
            }
        } else {
            for (int idx = 0; idx < NPTS; idx++) {
                const float4 p = pos[idx];
                const float p2 = __fadd_rn(__fmul_rn(p.x, p.x),
                                           __fmul_rn(p.y, p.y));
                const float scv = scores[idx];
                const float dot = __fmaf_rn(p.y, gy, __fmul_rn(p.x, gx));
                const float d2 = __fsub_rn(__fadd_rn(p2, g2),
                                           __fmul_rn(2.0f, dot));
                insert4(d2, idx, scv, da, db, dc, dd, ia, ib, ic, id_,
                        sa, sb, sc_, sd);
            }
        }

        // Finalize: sqrt only for the 4 finalists; filter + strict-> argmax.
        const float f0 = sqrtf(fmaxf(da, 1e-12f));
        const float f1 = sqrtf(fmaxf(db, 1e-12f));
        const float f2 = sqrtf(fmaxf(dc, 1e-12f));
        const float f3 = sqrtf(fmaxf(dd, 1e-12f));
        const float thr = __fmul_rn(2.0f, f0);   // exact (power of 2)

        float best = NEG_INF_F;
        int bestid = 0;
        if (f0 <= thr && f0 < dist_max && sa  > best) { best = sa;  bestid = ia; }
        if (f1 <= thr && f1 < dist_max && sb  > best) { best = sb;  bestid = ib; }
        if (f2 <= thr && f2 < dist_max && sc_ > best) { best = sc_; bestid = ic; }
        if (f3 <= thr && f3 < dist_max && sd  > best) { best = sd;  bestid = id_; }

        if (best > a45.x) {
            const float4 pr = pos[bestid];
            r0 = pr.x; r1 = pr.y; r2 = pr.z; r3 = pr.w; r4 = best; r5 = code;
        } else {
            r0 = a01.x; r1 = a01.y; r2 = a23.x; r3 = a23.y;
            r4 = a45.x; r5 = a45.y;
        }
    }
    __syncthreads();   // s_buck dead; safe to overlay with output staging

    // ---- Phase C: stage rows in smem, flush coalesced float4 stores ----
    float* s_out = (float*)s_buck;        // 6 KB staging inside s_buck
    if (is_g) {
        const int b = tid * 6;
        s_out[b + 0] = r0; s_out[b + 1] = r1; s_out[b + 2] = r2;
        s_out[b + 3] = r3; s_out[b + 4] = r4; s_out[b + 5] = r5;
    }
    __syncthreads();

    float4* gout = (float4*)(out + (size_t)blockIdx.x * GPTS * 6);
    const float4* s_out4 = (const float4*)s_out;
    if (tid < GPTS * 6 / 4)               // 384 float4 stores
        gout[tid] = s_out4[tid];
}

// ---------------------------------------------------------------------------
// Inputs (metadata order): pos (4096,4) f32, scores (4096,) f32,
// grid (65536,2) f32, accu (65536,6) f32, scale () f32, code () f32.
// ---------------------------------------------------------------------------
extern "C" void kernel_launch(void* const* d_in, const int* in_sizes, int n_in,
                              void* d_out, int out_size)
{
    const float4* pos    = (const float4*)d_in[0];
    const float*  scores = (const float*) d_in[1];
    const float2* grid   = (const float2*)d_in[2];
    const float*  accu   = (const float*) d_in[3];
    const float*  scale  = (const float*) d_in[4];
    const float*  code   = (const float*) d_in[5];
    float* out = (float*)d_out;

    pump_fused_kernel<<<NBLK, BLOCK_T>>>(pos, scores, grid, accu,
                                         scale, code, out);
}